// round 13
// baseline (speedup 1.0000x reference)
#include <cuda_runtime.h>
#include <cstdint>

// ComparatorNBit: A,B float32 [N,32] in {0,1}, MSB first.
// Exact Boolean algebra => 32-bit unsigned compare of packed words.
//   d_out[0..N) = a_gt_b,  d_out[N..2N) = a_eq_b
//
// R10 winner (default caching, 8 rows/group, MLP=16 front-batched LDG.128,
// FFMA nibble pack + ballot priority, float4 stores) with ONE change:
// block=64 for finer CTA packing (~28 warps/SM resident at 72 regs vs ~24
// at block=128) -> more outstanding loads SM-wide, smoother tail balance.

#define ROWS_PER_GROUP 8

__device__ __forceinline__ float nibf(const float4& v) {
    return fmaf(v.x, 8.0f, fmaf(v.y, 4.0f, fmaf(v.z, 2.0f, v.w)));
}

__global__ void __launch_bounds__(64) comparator_nbit_kernel(
    const float4* __restrict__ A4,
    const float4* __restrict__ B4,
    float* __restrict__ out,
    int n)
{
    int gid = blockIdx.x * blockDim.x + threadIdx.x;
    int g   = gid >> 3;                 // group: rows 8g .. 8g+7
    int sub = gid & 7;                  // 16B chunk within a row (0 = MSBs)
    int r0  = g << 3;
    if (r0 >= n) return;

    float4 a[ROWS_PER_GROUP], b[ROWS_PER_GROUP];
    if (r0 + ROWS_PER_GROUP - 1 < n) {
        size_t base = (size_t)r0 * 8 + sub;
        #pragma unroll
        for (int i = 0; i < ROWS_PER_GROUP; i++) {
            a[i] = A4[base + 8 * i];
            b[i] = B4[base + 8 * i];
        }
    } else {
        #pragma unroll
        for (int i = 0; i < ROWS_PER_GROUP; i++) {   // tail: clamp, extras discarded
            int r = min(r0 + i, n - 1);
            size_t idx = (size_t)r * 8 + sub;
            a[i] = A4[idx];
            b[i] = B4[idx];
        }
    }

    unsigned bal_ne[ROWS_PER_GROUP], bal_gt[ROWS_PER_GROUP];
    #pragma unroll
    for (int i = 0; i < ROWS_PER_GROUP; i++) {
        float fa = nibf(a[i]);
        float fb = nibf(b[i]);
        bal_ne[i] = __ballot_sync(0xffffffffu, fa != fb);
        bal_gt[i] = __ballot_sync(0xffffffffu, fa >  fb);
    }

    if (sub == 0) {
        unsigned shift = threadIdx.x & 24u;   // this group's byte of the ballot
        float gtv[ROWS_PER_GROUP], eqv[ROWS_PER_GROUP];
        #pragma unroll
        for (int i = 0; i < ROWS_PER_GROUP; i++) {
            unsigned ne8 = (bal_ne[i] >> shift) & 0xFFu;
            unsigned lsb = ne8 & (0u - ne8);  // first differing nibble (MSB-first)
            gtv[i] = ((bal_gt[i] >> shift) & lsb) ? 1.0f : 0.0f;
            eqv[i] = (ne8 == 0u) ? 1.0f : 0.0f;
        }
        if ((r0 + ROWS_PER_GROUP - 1 < n) && ((n & 7) == 0)) {
            *(float4*)(out + r0)         = make_float4(gtv[0], gtv[1], gtv[2], gtv[3]);
            *(float4*)(out + r0 + 4)     = make_float4(gtv[4], gtv[5], gtv[6], gtv[7]);
            *(float4*)(out + n + r0)     = make_float4(eqv[0], eqv[1], eqv[2], eqv[3]);
            *(float4*)(out + n + r0 + 4) = make_float4(eqv[4], eqv[5], eqv[6], eqv[7]);
        } else {
            #pragma unroll
            for (int i = 0; i < ROWS_PER_GROUP; i++)
                if (r0 + i < n) {
                    out[r0 + i]     = gtv[i];
                    out[n + r0 + i] = eqv[i];
                }
        }
    }
}

extern "C" void kernel_launch(void* const* d_in, const int* in_sizes, int n_in,
                              void* d_out, int out_size)
{
    const float4* A4 = (const float4*)d_in[0];
    const float4* B4 = (const float4*)d_in[1];
    float* out = (float*)d_out;

    int n = in_sizes[0] / 32;                            // rows
    long long groups = (n + ROWS_PER_GROUP - 1) / ROWS_PER_GROUP;
    long long total_threads = groups * 8;
    int block = 64;
    int grid = (int)((total_threads + block - 1) / block);

    comparator_nbit_kernel<<<grid, block>>>(A4, B4, out, n);
}

// round 15
// speedup vs baseline: 1.0122x; 1.0122x over previous
#include <cuda_runtime.h>
#include <cstdint>

// ComparatorNBit: A,B float32 [N,32] in {0,1}, MSB first.
// Exact Boolean algebra => 32-bit unsigned compare of packed words.
//   d_out[0..N) = a_gt_b,  d_out[N..2N) = a_eq_b
//
// R10 core (block=128, FFMA nibble pack + ballot priority, default caching)
// retuned for register-limited residency: 6 rows per 8-lane group
// (12 front-batched LDG.128/thread, ~56 regs) with __launch_bounds__(128,9)
// -> 9 CTAs/SM = 36 warps resident = 432 in-flight lane-loads/SM
// (+12.5% vs R10's 384). Stores: 3x float2 per output array (r0=6g even).

#define RPG 6

__device__ __forceinline__ float nibf(const float4& v) {
    return fmaf(v.x, 8.0f, fmaf(v.y, 4.0f, fmaf(v.z, 2.0f, v.w)));
}

__global__ void __launch_bounds__(128, 9) comparator_nbit_kernel(
    const float4* __restrict__ A4,
    const float4* __restrict__ B4,
    float* __restrict__ out,
    int n)
{
    int gid = blockIdx.x * blockDim.x + threadIdx.x;
    int g   = gid >> 3;                 // group: rows 6g .. 6g+5
    int sub = gid & 7;                  // 16B chunk within a row (0 = MSBs)
    int r0  = g * RPG;
    if (r0 >= n) return;

    float4 a[RPG], b[RPG];
    if (r0 + RPG - 1 < n) {
        size_t base = (size_t)r0 * 8 + sub;
        #pragma unroll
        for (int i = 0; i < RPG; i++) {
            a[i] = A4[base + 8 * i];
            b[i] = B4[base + 8 * i];
        }
    } else {
        #pragma unroll
        for (int i = 0; i < RPG; i++) {   // tail: clamp, extras discarded
            int r = min(r0 + i, n - 1);
            size_t idx = (size_t)r * 8 + sub;
            a[i] = A4[idx];
            b[i] = B4[idx];
        }
    }

    unsigned bal_ne[RPG], bal_gt[RPG];
    #pragma unroll
    for (int i = 0; i < RPG; i++) {
        float fa = nibf(a[i]);
        float fb = nibf(b[i]);
        bal_ne[i] = __ballot_sync(0xffffffffu, fa != fb);
        bal_gt[i] = __ballot_sync(0xffffffffu, fa >  fb);
    }

    if (sub == 0) {
        unsigned shift = threadIdx.x & 24u;   // this group's byte of the ballot
        float gtv[RPG], eqv[RPG];
        #pragma unroll
        for (int i = 0; i < RPG; i++) {
            unsigned ne8 = (bal_ne[i] >> shift) & 0xFFu;
            unsigned lsb = ne8 & (0u - ne8);  // first differing nibble (MSB-first)
            gtv[i] = ((bal_gt[i] >> shift) & lsb) ? 1.0f : 0.0f;
            eqv[i] = (ne8 == 0u) ? 1.0f : 0.0f;
        }
        if (r0 + RPG - 1 < n) {   // full group: r0 = 6g is even -> float2 aligned
            #pragma unroll
            for (int i = 0; i < RPG; i += 2) {
                *(float2*)(out + r0 + i)     = make_float2(gtv[i], gtv[i + 1]);
                *(float2*)(out + n + r0 + i) = make_float2(eqv[i], eqv[i + 1]);
            }
        } else {
            #pragma unroll
            for (int i = 0; i < RPG; i++)
                if (r0 + i < n) {
                    out[r0 + i]     = gtv[i];
                    out[n + r0 + i] = eqv[i];
                }
        }
    }
}

extern "C" void kernel_launch(void* const* d_in, const int* in_sizes, int n_in,
                              void* d_out, int out_size)
{
    const float4* A4 = (const float4*)d_in[0];
    const float4* B4 = (const float4*)d_in[1];
    float* out = (float*)d_out;

    int n = in_sizes[0] / 32;                            // rows
    long long groups = (n + RPG - 1) / RPG;
    long long total_threads = groups * 8;
    int block = 128;
    int grid = (int)((total_threads + block - 1) / block);

    comparator_nbit_kernel<<<grid, block>>>(A4, B4, out, n);
}